// round 11
// baseline (speedup 1.0000x reference)
#include <cuda_runtime.h>
#include <cuda_bf16.h>
#include <math.h>

#define SQ 2048
#define BB 2
#define NH 8
#define DK 64
#define DM 512

__device__ float g_q[BB*NH*SQ*DK];
__device__ float g_v[BB*NH*SQ*DK];
__device__ float g_o[BB*NH*SQ*DK];
__device__ float g_tbl[NH*4096];
// pre-split pair tiles: per (bh,kb): hi[64*36] | lo[64*36]  (unsigned bf16x2)
__device__ unsigned g_kst[BB*NH*32*4608];
__device__ unsigned g_vst[BB*NH*32*4608];

// bf16 m16n8k16 MMA (sm_80+ baseline)
__device__ __forceinline__ void mma16(float* d, const unsigned* a, const unsigned* b){
    asm volatile("mma.sync.aligned.m16n8k16.row.col.f32.bf16.bf16.f32 "
        "{%0,%1,%2,%3}, {%4,%5,%6,%7}, {%8,%9}, {%0,%1,%2,%3};"
        : "+f"(d[0]), "+f"(d[1]), "+f"(d[2]), "+f"(d[3])
        : "r"(a[0]), "r"(a[1]), "r"(a[2]), "r"(a[3]), "r"(b[0]), "r"(b[1]));
}

__device__ __forceinline__ void bfsplit(float a, float b, unsigned& hi, unsigned& lo){
    __nv_bfloat162 h2 = __floats2bfloat162_rn(a, b);
    float ra = a - __bfloat162float(h2.x);
    float rb = b - __bfloat162float(h2.y);
    __nv_bfloat162 l2 = __floats2bfloat162_rn(ra, rb);
    hi = *(unsigned*)&h2;
    lo = *(unsigned*)&l2;
}

__device__ __forceinline__ unsigned smem_u32a(const void* p){
    unsigned a;
    asm("{ .reg .u64 t; cvta.to.shared.u64 t, %1; cvt.u32.u64 %0, t; }" : "=r"(a) : "l"(p));
    return a;
}
__device__ __forceinline__ void cp16(unsigned saddr, const void* g){
    asm volatile("cp.async.cg.shared.global [%0], [%1], 16;" :: "r"(saddr), "l"(g) : "memory");
}
#define CP_COMMIT() asm volatile("cp.async.commit_group;" ::: "memory")
#define CP_WAIT(n)  asm volatile("cp.async.wait_group %0;" :: "n"(n) : "memory")

// ---------------------------------------------------------------------------
// Bias distance table (exact HF T5 bucketing)
// ---------------------------------------------------------------------------
__global__ void tbl_kernel(const float* __restrict__ emb){
    for (int i = threadIdx.x; i < 4096; i += 256){
        int rp = i - 2047;
        int bucket = (rp > 0) ? 16 : 0;
        int rel = (rp < 0) ? -rp : rp;
        int v;
        if (rel < 8) v = rel;
        else {
            float tt = logf((float)rel * 0.125f) / 2.772588722239781f * 8.0f;
            int vi = (int)tt;
            v = 8 + (vi < 7 ? vi : 7);
        }
        bucket += v;
        #pragma unroll
        for (int h = 0; h < NH; h++)
            g_tbl[h*4096 + i] = emb[bucket*NH + h];
    }
}

// ---------------------------------------------------------------------------
// QKV projection: X[4096,512] @ W[512,512], bf16 3-product, tile 128x64.
// z==1 (K): writes pre-split hi/lo pair tiles to g_kst directly.
// ---------------------------------------------------------------------------
__global__ __launch_bounds__(256, 2) void qkv_bf(const float* __restrict__ X,
        const float* __restrict__ Wq, const float* __restrict__ Wk,
        const float* __restrict__ Wv){
    extern __shared__ unsigned smq[];
    unsigned* Ahp = smq;                 // 128*20
    unsigned* Alp = Ahp + 2560;
    unsigned* Bhp = Alp + 2560;          // 16*68
    unsigned* Blp = Bhp + 1088;

    int z = blockIdx.z;
    const float* W = (z==0)?Wq:(z==1)?Wk:Wv;

    int m0 = blockIdx.y*128, n0 = blockIdx.x*64;
    int tid = threadIdx.x, lane = tid&31, warp = tid>>5;
    int g = lane>>2, t = lane&3, wm = warp*16;

    float acc[8][4] = {};

    for (int k0 = 0; k0 < DM; k0 += 32){
        #pragma unroll
        for (int i = 0; i < 4; i++){
            int r = (tid>>3) + 32*i;
            int c4 = tid & 7;
            float4 v = *(const float4*)&X[(size_t)(m0+r)*DM + k0 + 4*c4];
            bfsplit(v.x, v.y, Ahp[r*20 + 2*c4],     Alp[r*20 + 2*c4]);
            bfsplit(v.z, v.w, Ahp[r*20 + 2*c4 + 1], Alp[r*20 + 2*c4 + 1]);
        }
        {
            int n = tid & 63, kp0 = tid >> 6;
            #pragma unroll
            for (int i = 0; i < 4; i++){
                int kp = kp0 + 4*i;
                float b0 = W[(size_t)(k0 + 2*kp)*DM + n0 + n];
                float b1 = W[(size_t)(k0 + 2*kp + 1)*DM + n0 + n];
                bfsplit(b0, b1, Bhp[kp*68 + n], Blp[kp*68 + n]);
            }
        }
        __syncthreads();

        #pragma unroll
        for (int ks = 0; ks < 2; ks++){
            unsigned ah[4] = {
                Ahp[(wm+g)*20   + t + 8*ks],
                Ahp[(wm+g+8)*20 + t + 8*ks],
                Ahp[(wm+g)*20   + t + 4 + 8*ks],
                Ahp[(wm+g+8)*20 + t + 4 + 8*ks] };
            unsigned al[4] = {
                Alp[(wm+g)*20   + t + 8*ks],
                Alp[(wm+g+8)*20 + t + 8*ks],
                Alp[(wm+g)*20   + t + 4 + 8*ks],
                Alp[(wm+g+8)*20 + t + 4 + 8*ks] };
            #pragma unroll
            for (int j = 0; j < 8; j++){
                int n = 8*j + g;
                unsigned bh2[2] = { Bhp[(t+8*ks)*68 + n], Bhp[(t+4+8*ks)*68 + n] };
                unsigned bl2[2] = { Blp[(t+8*ks)*68 + n], Blp[(t+4+8*ks)*68 + n] };
                mma16(acc[j], ah, bh2);
                mma16(acc[j], al, bh2);
                mma16(acc[j], ah, bl2);
            }
        }
        __syncthreads();
    }

    int m_ = m0 + wm + g;
    int b = m_ >> 11;
    int s1 = m_ & 2047, s2 = (m_+8) & 2047;

    if (z == 1){
        // write K directly as split pair tiles (same values split_kernel produced)
        int h = n0 >> 6;
        int kb = s1 >> 6;                 // s2 is in the same 64-row tile
        int r1 = s1 & 63, r2 = s2 & 63;
        unsigned* base = g_kst + (size_t)((b*NH + h)*32 + kb)*4608;
        #pragma unroll
        for (int j = 0; j < 8; j++){
            int kp = 4*j + t;             // d-pair index: d = 8j+2t
            unsigned hi, lo;
            bfsplit(acc[j][0], acc[j][1], hi, lo);
            base[r1*36 + kp] = hi; base[2304 + r1*36 + kp] = lo;
            bfsplit(acc[j][2], acc[j][3], hi, lo);
            base[r2*36 + kp] = hi; base[2304 + r2*36 + kp] = lo;
        }
    } else {
        float* out = (z==0) ? g_q : g_v;
        #pragma unroll
        for (int j = 0; j < 8; j++){
            int n = n0 + 8*j + 2*t;
            int h = n >> 6, d = n & 63;
            size_t hb = (size_t)(b*NH + h) * SQ;
            *(float2*)&out[((hb + s1) << 6) + d] = make_float2(acc[j][0], acc[j][1]);
            *(float2*)&out[((hb + s2) << 6) + d] = make_float2(acc[j][2], acc[j][3]);
        }
    }
}

// ---------------------------------------------------------------------------
// Split V^T (pairs along seq) into hi/lo pair tiles.
// ---------------------------------------------------------------------------
__global__ __launch_bounds__(128) void split_kernel(){
    int kb = blockIdx.x, bh = blockIdx.y;
    const float* Vin = g_v + ((size_t)bh*SQ + kb*64)*DK;
    unsigned* Vh = g_vst + (size_t)(bh*32+kb)*4608;
    unsigned* Vl = Vh + 2304;
    int t = threadIdx.x;
    #pragma unroll
    for (int i = 0; i < 16; i++){
        int e = t + 128*i;
        int d = e & 63, kp = e >> 6;
        float v0 = Vin[(2*kp)*64 + d];
        float v1 = Vin[(2*kp + 1)*64 + d];
        bfsplit(v0, v1, Vh[d*36 + kp], Vl[d*36 + kp]);
    }
}

// ---------------------------------------------------------------------------
// Flash attention + bias writer. Grid = 296 CTAs (one full wave):
//  bid < 256  : attention for (bh = bid>>4, q0 = (bid&15)*128)
//  bid >= 256 : 40 writer CTAs stream bias output [8,2048,2048] from g_tbl
// ---------------------------------------------------------------------------
__global__ __launch_bounds__(256, 2) void attn_bf(float* __restrict__ bias_out){
    int bid = blockIdx.x;
    int tid = threadIdx.x;

    if (bid >= 256){
        // bias writer: 8.39M float4 across 40 CTAs * 256 threads
        float4* out4 = (float4*)bias_out;
        const int NT = 40*256;
        for (int f = (bid-256)*256 + tid; f < 8*1048576; f += NT){
            int h = f >> 20;
            int rem = f & 1048575;
            int q = rem >> 9;
            int k4 = (rem & 511) << 2;
            const float* tp = g_tbl + h*4096 + (k4 - q + 2047);
            out4[f] = make_float4(__ldg(tp), __ldg(tp+1), __ldg(tp+2), __ldg(tp+3));
        }
        return;
    }

    extern __shared__ float smf[];
    float* tb = smf;
    unsigned* U = (unsigned*)smf;
    unsigned sbase = smem_u32a(smf);

    int lane = tid&31, warp = tid>>5;
    int g = lane>>2, t = lane&3, wm = warp*16;
    int bh = bid >> 4, h = bh & 7, q0 = (bid & 15)*128;

    const uint4* kst4 = (const uint4*)g_kst;
    const uint4* vst4 = (const uint4*)g_vst;

    // issue cp.async for tile 0 into buf0
    {
        size_t kb4 = (size_t)(bh*32) * 1152;
        unsigned dK = sbase + 4096u*4;
        unsigned dV = dK + 4608u*4;
        #pragma unroll
        for (int i = 0; i < 4; i++){
            int e = tid + 256*i;
            cp16(dK + 16u*e, &kst4[kb4 + e]);
            cp16(dV + 16u*e, &vst4[kb4 + e]);
        }
        if (tid < 128){
            cp16(dK + 16u*(1024 + tid), &kst4[kb4 + 1024 + tid]);
            cp16(dV + 16u*(1024 + tid), &vst4[kb4 + 1024 + tid]);
        }
        CP_COMMIT();
    }

    // overlap: bias table + Q fragments
    for (int i = tid; i < 4096; i += 256) tb[i] = g_tbl[h*4096 + i];

    unsigned qh[4][4], ql[4][4];
    {
        const float* Qg = g_q + ((size_t)bh*SQ + q0 + wm)*DK;
        #pragma unroll
        for (int ks = 0; ks < 4; ks++){
            float2 v00 = *(const float2*)&Qg[g*64      + 2*t + 16*ks];
            float2 v10 = *(const float2*)&Qg[(g+8)*64  + 2*t + 16*ks];
            float2 v02 = *(const float2*)&Qg[g*64      + 2*t + 8 + 16*ks];
            float2 v12 = *(const float2*)&Qg[(g+8)*64  + 2*t + 8 + 16*ks];
            bfsplit(v00.x, v00.y, qh[ks][0], ql[ks][0]);
            bfsplit(v10.x, v10.y, qh[ks][1], ql[ks][1]);
            bfsplit(v02.x, v02.y, qh[ks][2], ql[ks][2]);
            bfsplit(v12.x, v12.y, qh[ks][3], ql[ks][3]);
        }
    }

    float oacc[8][4] = {};
    float l0 = 0.f, l1 = 0.f;
    int bb_const = 2047 - (q0 + wm + g) + 2*t;

    for (int ib = 0; ib < 32; ib++){
        if (ib + 1 < 32){
            size_t kb4 = (size_t)(bh*32 + ib + 1) * 1152;
            unsigned ub = 4096u + ((unsigned)(ib+1) & 1u) * 9216u;
            unsigned dK = sbase + ub*4;
            unsigned dV = dK + 4608u*4;
            #pragma unroll
            for (int i = 0; i < 4; i++){
                int e = tid + 256*i;
                cp16(dK + 16u*e, &kst4[kb4 + e]);
                cp16(dV + 16u*e, &vst4[kb4 + e]);
            }
            if (tid < 128){
                cp16(dK + 16u*(1024 + tid), &kst4[kb4 + 1024 + tid]);
                cp16(dV + 16u*(1024 + tid), &vst4[kb4 + 1024 + tid]);
            }
            CP_COMMIT();
            CP_WAIT(1);
        } else {
            CP_WAIT(0);
        }
        __syncthreads();

        unsigned base = 4096u + ((unsigned)ib & 1u) * 9216u;
        unsigned bKh = base, bKl = base + 2304, bVh = base + 4608, bVl = base + 6912;
        int kb = ib*64;

        #pragma unroll
        for (int half = 0; half < 2; half++){
            float s[4][4] = {};
            #pragma unroll
            for (int ks = 0; ks < 4; ks++){
                #pragma unroll
                for (int j = 0; j < 4; j++){
                    int seq = 8*(4*half + j) + g;
                    unsigned bh2[2] = { U[bKh + seq*36 + t + 8*ks],
                                        U[bKh + seq*36 + t + 4 + 8*ks] };
                    unsigned bl2[2] = { U[bKl + seq*36 + t + 8*ks],
                                        U[bKl + seq*36 + t + 4 + 8*ks] };
                    mma16(s[j], qh[ks], bh2);
                    mma16(s[j], ql[ks], bh2);
                    mma16(s[j], qh[ks], bl2);
                }
            }

            int bb = bb_const + kb + 32*half;
            unsigned pah[2][4], pal[2][4];
            #pragma unroll
            for (int j = 0; j < 4; j++){
                float p0 = __expf(s[j][0] + tb[bb + 8*j]);
                float p1 = __expf(s[j][1] + tb[bb + 8*j + 1]);
                float p2 = __expf(s[j][2] + tb[bb + 8*j - 8]);
                float p3 = __expf(s[j][3] + tb[bb + 8*j - 7]);
                l0 += p0 + p1;
                l1 += p2 + p3;
                int i = j >> 1;
                if ((j & 1) == 0){
                    bfsplit(p0, p1, pah[i][0], pal[i][0]);
                    bfsplit(p2, p3, pah[i][1], pal[i][1]);
                } else {
                    bfsplit(p0, p1, pah[i][2], pal[i][2]);
                    bfsplit(p2, p3, pah[i][3], pal[i][3]);
                }
            }

            #pragma unroll
            for (int i = 0; i < 2; i++){
                int ksp = 2*half + i;
                #pragma unroll
                for (int j = 0; j < 8; j++){
                    int d = 8*j + g;
                    unsigned vh2[2] = { U[bVh + d*36 + t + 8*ksp],
                                        U[bVh + d*36 + t + 4 + 8*ksp] };
                    unsigned vl2[2] = { U[bVl + d*36 + t + 8*ksp],
                                        U[bVl + d*36 + t + 4 + 8*ksp] };
                    mma16(oacc[j], pah[i], vh2);
                    mma16(oacc[j], pal[i], vh2);
                    mma16(oacc[j], pah[i], vl2);
                }
            }
        }
        __syncthreads();
    }

    l0 += __shfl_xor_sync(0xffffffffu, l0, 1);
    l0 += __shfl_xor_sync(0xffffffffu, l0, 2);
    l1 += __shfl_xor_sync(0xffffffffu, l1, 1);
    l1 += __shfl_xor_sync(0xffffffffu, l1, 2);
    float inv0 = 1.f / l0, inv1 = 1.f / l1;

    float* Og = g_o + ((size_t)bh*SQ + q0 + wm)*DK;
    #pragma unroll
    for (int j = 0; j < 8; j++){
        int d = 8*j + 2*t;
        *(float2*)&Og[g*64 + d]     = make_float2(oacc[j][0]*inv0, oacc[j][1]*inv0);
        *(float2*)&Og[(g+8)*64 + d] = make_float2(oacc[j][2]*inv1, oacc[j][3]*inv1);
    }
}

// ---------------------------------------------------------------------------
// Output projection: gather O as [4096,512] @ Wo[512,512], bf16 3-product.
// ---------------------------------------------------------------------------
__global__ __launch_bounds__(256, 2) void outproj_bf(const float* __restrict__ Wo,
                                                     float* __restrict__ out){
    extern __shared__ unsigned smq[];
    unsigned* Ahp = smq;
    unsigned* Alp = Ahp + 2560;
    unsigned* Bhp = Alp + 2560;
    unsigned* Blp = Bhp + 1088;

    int m0 = blockIdx.y*128, n0 = blockIdx.x*64;
    int tid = threadIdx.x, lane = tid&31, warp = tid>>5;
    int g = lane>>2, t = lane&3, wm = warp*16;

    float acc[8][4] = {};

    for (int k0 = 0; k0 < DM; k0 += 32){
        #pragma unroll
        for (int i = 0; i < 4; i++){
            int r = (tid>>3) + 32*i;
            int c4 = tid & 7;
            int kg = k0 + 4*c4;
            int hh = kg >> 6, d0 = kg & 63;
            int mg = m0 + r;
            int b = mg >> 11, s_ = mg & 2047;
            float4 v = *(const float4*)&g_o[(((size_t)(b*NH + hh)*SQ + s_) << 6) + d0];
            bfsplit(v.x, v.y, Ahp[r*20 + 2*c4],     Alp[r*20 + 2*c4]);
            bfsplit(v.z, v.w, Ahp[r*20 + 2*c4 + 1], Alp[r*20 + 2*c4 + 1]);
        }
        {
            int n = tid & 63, kp0 = tid >> 6;
            #pragma unroll
            for (int i = 0; i < 4; i++){
                int kp = kp0 + 4*i;
                float b0 = Wo[(size_t)(k0 + 2*kp)*DM + n0 + n];
                float b1 = Wo[(size_t)(k0 + 2*kp + 1)*DM + n0 + n];
                bfsplit(b0, b1, Bhp[kp*68 + n], Blp[kp*68 + n]);
            }
        }
        __syncthreads();

        #pragma unroll
        for (int ks = 0; ks < 2; ks++){
            unsigned ah[4] = {
                Ahp[(wm+g)*20   + t + 8*ks],
                Ahp[(wm+g+8)*20 + t + 8*ks],
                Ahp[(wm+g)*20   + t + 4 + 8*ks],
                Ahp[(wm+g+8)*20 + t + 4 + 8*ks] };
            unsigned al[4] = {
                Alp[(wm+g)*20   + t + 8*ks],
                Alp[(wm+g+8)*20 + t + 8*ks],
                Alp[(wm+g)*20   + t + 4 + 8*ks],
                Alp[(wm+g+8)*20 + t + 4 + 8*ks] };
            #pragma unroll
            for (int j = 0; j < 8; j++){
                int n = 8*j + g;
                unsigned bh2[2] = { Bhp[(t+8*ks)*68 + n], Bhp[(t+4+8*ks)*68 + n] };
                unsigned bl2[2] = { Blp[(t+8*ks)*68 + n], Blp[(t+4+8*ks)*68 + n] };
                mma16(acc[j], ah, bh2);
                mma16(acc[j], al, bh2);
                mma16(acc[j], ah, bl2);
            }
        }
        __syncthreads();
    }

    int m_ = m0 + wm + g;
    #pragma unroll
    for (int j = 0; j < 8; j++){
        int n = n0 + 8*j + 2*t;
        *(float2*)&out[(size_t)m_*DM + n]     = make_float2(acc[j][0], acc[j][1]);
        *(float2*)&out[(size_t)(m_+8)*DM + n] = make_float2(acc[j][2], acc[j][3]);
    }
}

// ---------------------------------------------------------------------------
extern "C" void kernel_launch(void* const* d_in, const int* in_sizes, int n_in,
                              void* d_out, int out_size) {
    const float* hs  = (const float*)d_in[0];
    const float* Wq  = (const float*)d_in[1];
    const float* Wk  = (const float*)d_in[2];
    const float* Wv  = (const float*)d_in[3];
    const float* Wo  = (const float*)d_in[4];
    const float* emb = (const float*)d_in[5];

    float* out_attn = (float*)d_out;
    float* out_bias = out_attn + (size_t)BB * SQ * DM;

    static bool attr_set = false;
    if (!attr_set) {
        cudaFuncSetAttribute(attn_bf, cudaFuncAttributeMaxDynamicSharedMemorySize, 90112);
        attr_set = true;
    }

    tbl_kernel<<<1, 256>>>(emb);
    qkv_bf<<<dim3(DM/64, (BB*SQ)/128, 3), 256, 29184>>>(hs, Wq, Wk, Wv);
    split_kernel<<<dim3(32, BB*NH), 128>>>();
    attn_bf<<<296, 256, 90112>>>(out_bias);
    outproj_bf<<<dim3(DM/64, (BB*SQ)/128), 256, 29184>>>(Wo, out_attn);
}

// round 12
// speedup vs baseline: 1.0091x; 1.0091x over previous
#include <cuda_runtime.h>
#include <cuda_bf16.h>
#include <math.h>

#define SQ 2048
#define BB 2
#define NH 8
#define DK 64
#define DM 512

__device__ float g_q[BB*NH*SQ*DK];
__device__ float g_v[BB*NH*SQ*DK];
__device__ float g_o[BB*NH*SQ*DK];
__device__ float g_tbl[NH*4096];
// pre-split pair tiles: per (bh,kb): hi[64*36] | lo[64*36]  (unsigned bf16x2)
__device__ unsigned g_kst[BB*NH*32*4608];
__device__ unsigned g_vst[BB*NH*32*4608];

// bf16 m16n8k16 MMA (sm_80+ baseline)
__device__ __forceinline__ void mma16(float* d, const unsigned* a, const unsigned* b){
    asm volatile("mma.sync.aligned.m16n8k16.row.col.f32.bf16.bf16.f32 "
        "{%0,%1,%2,%3}, {%4,%5,%6,%7}, {%8,%9}, {%0,%1,%2,%3};"
        : "+f"(d[0]), "+f"(d[1]), "+f"(d[2]), "+f"(d[3])
        : "r"(a[0]), "r"(a[1]), "r"(a[2]), "r"(a[3]), "r"(b[0]), "r"(b[1]));
}

__device__ __forceinline__ void bfsplit(float a, float b, unsigned& hi, unsigned& lo){
    __nv_bfloat162 h2 = __floats2bfloat162_rn(a, b);
    float ra = a - __bfloat162float(h2.x);
    float rb = b - __bfloat162float(h2.y);
    __nv_bfloat162 l2 = __floats2bfloat162_rn(ra, rb);
    hi = *(unsigned*)&h2;
    lo = *(unsigned*)&l2;
}

__device__ __forceinline__ unsigned smem_u32a(const void* p){
    unsigned a;
    asm("{ .reg .u64 t; cvta.to.shared.u64 t, %1; cvt.u32.u64 %0, t; }" : "=r"(a) : "l"(p));
    return a;
}
__device__ __forceinline__ void cp16(unsigned saddr, const void* g){
    asm volatile("cp.async.cg.shared.global [%0], [%1], 16;" :: "r"(saddr), "l"(g) : "memory");
}
#define CP_COMMIT() asm volatile("cp.async.commit_group;" ::: "memory")
#define CP_WAIT(n)  asm volatile("cp.async.wait_group %0;" :: "n"(n) : "memory")

// ---------------------------------------------------------------------------
// Bias distance table (exact HF T5 bucketing)
// ---------------------------------------------------------------------------
__global__ void tbl_kernel(const float* __restrict__ emb){
    for (int i = threadIdx.x; i < 4096; i += 256){
        int rp = i - 2047;
        int bucket = (rp > 0) ? 16 : 0;
        int rel = (rp < 0) ? -rp : rp;
        int v;
        if (rel < 8) v = rel;
        else {
            float tt = logf((float)rel * 0.125f) / 2.772588722239781f * 8.0f;
            int vi = (int)tt;
            v = 8 + (vi < 7 ? vi : 7);
        }
        bucket += v;
        #pragma unroll
        for (int h = 0; h < NH; h++)
            g_tbl[h*4096 + i] = emb[bucket*NH + h];
    }
}

// ---------------------------------------------------------------------------
// QKV projection: X[4096,512] @ W[512,512], bf16 3-product, tile 128x64.
// z==1 (K): writes pre-split hi/lo pair tiles to g_kst directly.
// ---------------------------------------------------------------------------
__global__ __launch_bounds__(256, 2) void qkv_bf(const float* __restrict__ X,
        const float* __restrict__ Wq, const float* __restrict__ Wk,
        const float* __restrict__ Wv){
    extern __shared__ unsigned smq[];
    unsigned* Ahp = smq;                 // 128*20
    unsigned* Alp = Ahp + 2560;
    unsigned* Bhp = Alp + 2560;          // 16*68
    unsigned* Blp = Bhp + 1088;

    int z = blockIdx.z;
    const float* W = (z==0)?Wq:(z==1)?Wk:Wv;

    int m0 = blockIdx.y*128, n0 = blockIdx.x*64;
    int tid = threadIdx.x, lane = tid&31, warp = tid>>5;
    int g = lane>>2, t = lane&3, wm = warp*16;

    float acc[8][4] = {};

    for (int k0 = 0; k0 < DM; k0 += 32){
        #pragma unroll
        for (int i = 0; i < 4; i++){
            int r = (tid>>3) + 32*i;
            int c4 = tid & 7;
            float4 v = *(const float4*)&X[(size_t)(m0+r)*DM + k0 + 4*c4];
            bfsplit(v.x, v.y, Ahp[r*20 + 2*c4],     Alp[r*20 + 2*c4]);
            bfsplit(v.z, v.w, Ahp[r*20 + 2*c4 + 1], Alp[r*20 + 2*c4 + 1]);
        }
        {
            int n = tid & 63, kp0 = tid >> 6;
            #pragma unroll
            for (int i = 0; i < 4; i++){
                int kp = kp0 + 4*i;
                float b0 = W[(size_t)(k0 + 2*kp)*DM + n0 + n];
                float b1 = W[(size_t)(k0 + 2*kp + 1)*DM + n0 + n];
                bfsplit(b0, b1, Bhp[kp*68 + n], Blp[kp*68 + n]);
            }
        }
        __syncthreads();

        #pragma unroll
        for (int ks = 0; ks < 2; ks++){
            unsigned ah[4] = {
                Ahp[(wm+g)*20   + t + 8*ks],
                Ahp[(wm+g+8)*20 + t + 8*ks],
                Ahp[(wm+g)*20   + t + 4 + 8*ks],
                Ahp[(wm+g+8)*20 + t + 4 + 8*ks] };
            unsigned al[4] = {
                Alp[(wm+g)*20   + t + 8*ks],
                Alp[(wm+g+8)*20 + t + 8*ks],
                Alp[(wm+g)*20   + t + 4 + 8*ks],
                Alp[(wm+g+8)*20 + t + 4 + 8*ks] };
            #pragma unroll
            for (int j = 0; j < 8; j++){
                int n = 8*j + g;
                unsigned bh2[2] = { Bhp[(t+8*ks)*68 + n], Bhp[(t+4+8*ks)*68 + n] };
                unsigned bl2[2] = { Blp[(t+8*ks)*68 + n], Blp[(t+4+8*ks)*68 + n] };
                mma16(acc[j], ah, bh2);
                mma16(acc[j], al, bh2);
                mma16(acc[j], ah, bl2);
            }
        }
        __syncthreads();
    }

    int m_ = m0 + wm + g;
    int b = m_ >> 11;
    int s1 = m_ & 2047, s2 = (m_+8) & 2047;

    if (z == 1){
        // write K directly as split pair tiles (same values split_kernel produced)
        int h = n0 >> 6;
        int kb = s1 >> 6;                 // s2 is in the same 64-row tile
        int r1 = s1 & 63, r2 = s2 & 63;
        unsigned* base = g_kst + (size_t)((b*NH + h)*32 + kb)*4608;
        #pragma unroll
        for (int j = 0; j < 8; j++){
            int kp = 4*j + t;             // d-pair index: d = 8j+2t
            unsigned hi, lo;
            bfsplit(acc[j][0], acc[j][1], hi, lo);
            base[r1*36 + kp] = hi; base[2304 + r1*36 + kp] = lo;
            bfsplit(acc[j][2], acc[j][3], hi, lo);
            base[r2*36 + kp] = hi; base[2304 + r2*36 + kp] = lo;
        }
    } else {
        float* out = (z==0) ? g_q : g_v;
        #pragma unroll
        for (int j = 0; j < 8; j++){
            int n = n0 + 8*j + 2*t;
            int h = n >> 6, d = n & 63;
            size_t hb = (size_t)(b*NH + h) * SQ;
            *(float2*)&out[((hb + s1) << 6) + d] = make_float2(acc[j][0], acc[j][1]);
            *(float2*)&out[((hb + s2) << 6) + d] = make_float2(acc[j][2], acc[j][3]);
        }
    }
}

// ---------------------------------------------------------------------------
// Split V^T (pairs along seq) into hi/lo pair tiles.
// ---------------------------------------------------------------------------
__global__ __launch_bounds__(128) void split_kernel(){
    int kb = blockIdx.x, bh = blockIdx.y;
    const float* Vin = g_v + ((size_t)bh*SQ + kb*64)*DK;
    unsigned* Vh = g_vst + (size_t)(bh*32+kb)*4608;
    unsigned* Vl = Vh + 2304;
    int t = threadIdx.x;
    #pragma unroll
    for (int i = 0; i < 16; i++){
        int e = t + 128*i;
        int d = e & 63, kp = e >> 6;
        float v0 = Vin[(2*kp)*64 + d];
        float v1 = Vin[(2*kp + 1)*64 + d];
        bfsplit(v0, v1, Vh[d*36 + kp], Vl[d*36 + kp]);
    }
}

// ---------------------------------------------------------------------------
// Flash attention + bias writer. Grid = 296 CTAs (one full wave):
//  bid < 256  : attention for (bh = bid>>4, q0 = (bid&15)*128)
//  bid >= 256 : 40 writer CTAs stream bias output [8,2048,2048] from g_tbl
// ---------------------------------------------------------------------------
__global__ __launch_bounds__(256, 2) void attn_bf(float* __restrict__ bias_out){
    int bid = blockIdx.x;
    int tid = threadIdx.x;

    if (bid >= 256){
        // bias writer: 8.39M float4 across 40 CTAs * 256 threads
        float4* out4 = (float4*)bias_out;
        const int NT = 40*256;
        for (int f = (bid-256)*256 + tid; f < 8*1048576; f += NT){
            int h = f >> 20;
            int rem = f & 1048575;
            int q = rem >> 9;
            int k4 = (rem & 511) << 2;
            const float* tp = g_tbl + h*4096 + (k4 - q + 2047);
            out4[f] = make_float4(__ldg(tp), __ldg(tp+1), __ldg(tp+2), __ldg(tp+3));
        }
        return;
    }

    extern __shared__ float smf[];
    float* tb = smf;
    unsigned* U = (unsigned*)smf;
    unsigned sbase = smem_u32a(smf);

    int lane = tid&31, warp = tid>>5;
    int g = lane>>2, t = lane&3, wm = warp*16;
    int bh = bid >> 4, h = bh & 7, q0 = (bid & 15)*128;

    const uint4* kst4 = (const uint4*)g_kst;
    const uint4* vst4 = (const uint4*)g_vst;

    // issue cp.async for tile 0 into buf0
    {
        size_t kb4 = (size_t)(bh*32) * 1152;
        unsigned dK = sbase + 4096u*4;
        unsigned dV = dK + 4608u*4;
        #pragma unroll
        for (int i = 0; i < 4; i++){
            int e = tid + 256*i;
            cp16(dK + 16u*e, &kst4[kb4 + e]);
            cp16(dV + 16u*e, &vst4[kb4 + e]);
        }
        if (tid < 128){
            cp16(dK + 16u*(1024 + tid), &kst4[kb4 + 1024 + tid]);
            cp16(dV + 16u*(1024 + tid), &vst4[kb4 + 1024 + tid]);
        }
        CP_COMMIT();
    }

    // overlap: bias table + Q fragments
    for (int i = tid; i < 4096; i += 256) tb[i] = g_tbl[h*4096 + i];

    unsigned qh[4][4], ql[4][4];
    {
        const float* Qg = g_q + ((size_t)bh*SQ + q0 + wm)*DK;
        #pragma unroll
        for (int ks = 0; ks < 4; ks++){
            float2 v00 = *(const float2*)&Qg[g*64      + 2*t + 16*ks];
            float2 v10 = *(const float2*)&Qg[(g+8)*64  + 2*t + 16*ks];
            float2 v02 = *(const float2*)&Qg[g*64      + 2*t + 8 + 16*ks];
            float2 v12 = *(const float2*)&Qg[(g+8)*64  + 2*t + 8 + 16*ks];
            bfsplit(v00.x, v00.y, qh[ks][0], ql[ks][0]);
            bfsplit(v10.x, v10.y, qh[ks][1], ql[ks][1]);
            bfsplit(v02.x, v02.y, qh[ks][2], ql[ks][2]);
            bfsplit(v12.x, v12.y, qh[ks][3], ql[ks][3]);
        }
    }

    float oacc[8][4] = {};
    float l0 = 0.f, l1 = 0.f;
    int bb_const = 2047 - (q0 + wm + g) + 2*t;

    for (int ib = 0; ib < 32; ib++){
        if (ib + 1 < 32){
            size_t kb4 = (size_t)(bh*32 + ib + 1) * 1152;
            unsigned ub = 4096u + ((unsigned)(ib+1) & 1u) * 9216u;
            unsigned dK = sbase + ub*4;
            unsigned dV = dK + 4608u*4;
            #pragma unroll
            for (int i = 0; i < 4; i++){
                int e = tid + 256*i;
                cp16(dK + 16u*e, &kst4[kb4 + e]);
                cp16(dV + 16u*e, &vst4[kb4 + e]);
            }
            if (tid < 128){
                cp16(dK + 16u*(1024 + tid), &kst4[kb4 + 1024 + tid]);
                cp16(dV + 16u*(1024 + tid), &vst4[kb4 + 1024 + tid]);
            }
            CP_COMMIT();
            CP_WAIT(1);
        } else {
            CP_WAIT(0);
        }
        __syncthreads();

        unsigned base = 4096u + ((unsigned)ib & 1u) * 9216u;
        unsigned bKh = base, bKl = base + 2304, bVh = base + 4608, bVl = base + 6912;
        int kb = ib*64;

        #pragma unroll
        for (int half = 0; half < 2; half++){
            float s[4][4] = {};
            #pragma unroll
            for (int ks = 0; ks < 4; ks++){
                #pragma unroll
                for (int j = 0; j < 4; j++){
                    int seq = 8*(4*half + j) + g;
                    unsigned bh2[2] = { U[bKh + seq*36 + t + 8*ks],
                                        U[bKh + seq*36 + t + 4 + 8*ks] };
                    unsigned bl2[2] = { U[bKl + seq*36 + t + 8*ks],
                                        U[bKl + seq*36 + t + 4 + 8*ks] };
                    mma16(s[j], qh[ks], bh2);
                    mma16(s[j], ql[ks], bh2);
                    mma16(s[j], qh[ks], bl2);
                }
            }

            int bb = bb_const + kb + 32*half;
            unsigned pah[2][4], pal[2][4];
            #pragma unroll
            for (int j = 0; j < 4; j++){
                float p0 = __expf(s[j][0] + tb[bb + 8*j]);
                float p1 = __expf(s[j][1] + tb[bb + 8*j + 1]);
                float p2 = __expf(s[j][2] + tb[bb + 8*j - 8]);
                float p3 = __expf(s[j][3] + tb[bb + 8*j - 7]);
                l0 += p0 + p1;
                l1 += p2 + p3;
                int i = j >> 1;
                if ((j & 1) == 0){
                    bfsplit(p0, p1, pah[i][0], pal[i][0]);
                    bfsplit(p2, p3, pah[i][1], pal[i][1]);
                } else {
                    bfsplit(p0, p1, pah[i][2], pal[i][2]);
                    bfsplit(p2, p3, pah[i][3], pal[i][3]);
                }
            }

            #pragma unroll
            for (int i = 0; i < 2; i++){
                int ksp = 2*half + i;
                #pragma unroll
                for (int j = 0; j < 8; j++){
                    int d = 8*j + g;
                    unsigned vh2[2] = { U[bVh + d*36 + t + 8*ksp],
                                        U[bVh + d*36 + t + 4 + 8*ksp] };
                    unsigned vl2[2] = { U[bVl + d*36 + t + 8*ksp],
                                        U[bVl + d*36 + t + 4 + 8*ksp] };
                    mma16(oacc[j], pah[i], vh2);
                    mma16(oacc[j], pal[i], vh2);
                    mma16(oacc[j], pah[i], vl2);
                }
            }
        }
        __syncthreads();
    }

    l0 += __shfl_xor_sync(0xffffffffu, l0, 1);
    l0 += __shfl_xor_sync(0xffffffffu, l0, 2);
    l1 += __shfl_xor_sync(0xffffffffu, l1, 1);
    l1 += __shfl_xor_sync(0xffffffffu, l1, 2);
    float inv0 = 1.f / l0, inv1 = 1.f / l1;

    float* Og = g_o + ((size_t)bh*SQ + q0 + wm)*DK;
    #pragma unroll
    for (int j = 0; j < 8; j++){
        int d = 8*j + 2*t;
        *(float2*)&Og[g*64 + d]     = make_float2(oacc[j][0]*inv0, oacc[j][1]*inv0);
        *(float2*)&Og[(g+8)*64 + d] = make_float2(oacc[j][2]*inv1, oacc[j][3]*inv1);
    }
}

// ---------------------------------------------------------------------------
// Output projection: gather O as [4096,512] @ Wo[512,512], bf16 3-product.
// ---------------------------------------------------------------------------
__global__ __launch_bounds__(256, 2) void outproj_bf(const float* __restrict__ Wo,
                                                     float* __restrict__ out){
    extern __shared__ unsigned smq[];
    unsigned* Ahp = smq;
    unsigned* Alp = Ahp + 2560;
    unsigned* Bhp = Alp + 2560;
    unsigned* Blp = Bhp + 1088;

    int m0 = blockIdx.y*128, n0 = blockIdx.x*64;
    int tid = threadIdx.x, lane = tid&31, warp = tid>>5;
    int g = lane>>2, t = lane&3, wm = warp*16;

    float acc[8][4] = {};

    for (int k0 = 0; k0 < DM; k0 += 32){
        #pragma unroll
        for (int i = 0; i < 4; i++){
            int r = (tid>>3) + 32*i;
            int c4 = tid & 7;
            int kg = k0 + 4*c4;
            int hh = kg >> 6, d0 = kg & 63;
            int mg = m0 + r;
            int b = mg >> 11, s_ = mg & 2047;
            float4 v = *(const float4*)&g_o[(((size_t)(b*NH + hh)*SQ + s_) << 6) + d0];
            bfsplit(v.x, v.y, Ahp[r*20 + 2*c4],     Alp[r*20 + 2*c4]);
            bfsplit(v.z, v.w, Ahp[r*20 + 2*c4 + 1], Alp[r*20 + 2*c4 + 1]);
        }
        {
            int n = tid & 63, kp0 = tid >> 6;
            #pragma unroll
            for (int i = 0; i < 4; i++){
                int kp = kp0 + 4*i;
                float b0 = Wo[(size_t)(k0 + 2*kp)*DM + n0 + n];
                float b1 = Wo[(size_t)(k0 + 2*kp + 1)*DM + n0 + n];
                bfsplit(b0, b1, Bhp[kp*68 + n], Blp[kp*68 + n]);
            }
        }
        __syncthreads();

        #pragma unroll
        for (int ks = 0; ks < 2; ks++){
            unsigned ah[4] = {
                Ahp[(wm+g)*20   + t + 8*ks],
                Ahp[(wm+g+8)*20 + t + 8*ks],
                Ahp[(wm+g)*20   + t + 4 + 8*ks],
                Ahp[(wm+g+8)*20 + t + 4 + 8*ks] };
            unsigned al[4] = {
                Alp[(wm+g)*20   + t + 8*ks],
                Alp[(wm+g+8)*20 + t + 8*ks],
                Alp[(wm+g)*20   + t + 4 + 8*ks],
                Alp[(wm+g+8)*20 + t + 4 + 8*ks] };
            #pragma unroll
            for (int j = 0; j < 8; j++){
                int n = 8*j + g;
                unsigned bh2[2] = { Bhp[(t+8*ks)*68 + n], Bhp[(t+4+8*ks)*68 + n] };
                unsigned bl2[2] = { Blp[(t+8*ks)*68 + n], Blp[(t+4+8*ks)*68 + n] };
                mma16(acc[j], ah, bh2);
                mma16(acc[j], al, bh2);
                mma16(acc[j], ah, bl2);
            }
        }
        __syncthreads();
    }

    int m_ = m0 + wm + g;
    #pragma unroll
    for (int j = 0; j < 8; j++){
        int n = n0 + 8*j + 2*t;
        *(float2*)&out[(size_t)m_*DM + n]     = make_float2(acc[j][0], acc[j][1]);
        *(float2*)&out[(size_t)(m_+8)*DM + n] = make_float2(acc[j][2], acc[j][3]);
    }
}

// ---------------------------------------------------------------------------
extern "C" void kernel_launch(void* const* d_in, const int* in_sizes, int n_in,
                              void* d_out, int out_size) {
    const float* hs  = (const float*)d_in[0];
    const float* Wq  = (const float*)d_in[1];
    const float* Wk  = (const float*)d_in[2];
    const float* Wv  = (const float*)d_in[3];
    const float* Wo  = (const float*)d_in[4];
    const float* emb = (const float*)d_in[5];

    float* out_attn = (float*)d_out;
    float* out_bias = out_attn + (size_t)BB * SQ * DM;

    static bool attr_set = false;
    if (!attr_set) {
        cudaFuncSetAttribute(attn_bf, cudaFuncAttributeMaxDynamicSharedMemorySize, 90112);
        attr_set = true;
    }

    tbl_kernel<<<1, 256>>>(emb);
    qkv_bf<<<dim3(DM/64, (BB*SQ)/128, 3), 256, 29184>>>(hs, Wq, Wk, Wv);
    split_kernel<<<dim3(32, BB*NH), 128>>>();
    attn_bf<<<296, 256, 90112>>>(out_bias);
    outproj_bf<<<dim3(DM/64, (BB*SQ)/128), 256, 29184>>>(Wo, out_attn);
}